// round 10
// baseline (speedup 1.0000x reference)
#include <cuda_runtime.h>
#include <cstdint>

// Problem constants
#define B_   4
#define T_   2048
#define C_   1024
#define H_   128
#define BT_  (B_ * T_)

typedef unsigned long long u64;

// ---------------------------------------------------------------------------
// f32x2 packed-math helpers (Blackwell sm_10x: SASS FFMA2 — 2 fp32 FMAs/inst)
// ---------------------------------------------------------------------------
__device__ __forceinline__ u64 bcast2(float x) {
    u64 r; asm("mov.b64 %0, {%1,%2};" : "=l"(r) : "f"(x), "f"(x)); return r;
}
__device__ __forceinline__ void fma2(u64& d, u64 a, u64 b) {
    asm("fma.rn.f32x2 %0, %1, %2, %0;" : "+l"(d) : "l"(a), "l"(b));
}
__device__ __forceinline__ void mul2(u64& d, u64 a) {
    asm("mul.rn.f32x2 %0, %0, %1;" : "+l"(d) : "l"(a));
}
__device__ __forceinline__ void unpack2(u64 v, float& x, float& y) {
    asm("mov.b64 {%0,%1}, %2;" : "=f"(x), "=f"(y) : "l"(v));
}

// Scratch for Q, K, V projections (4 MB each) — __device__ globals per alloc rules.
__device__ float g_q[BT_ * H_];
__device__ float g_k[BT_ * H_];
__device__ float g_v[BT_ * H_];

// ---------------------------------------------------------------------------
// Kernel 1: fused QKV projection.  out[m, n] = sum_k x[m,k] * W[k,n]
// M = 8192, K = 1024, N = 128.  Block tile 64x128, 256 threads, 4x8/thread,
// inner product via packed f32x2 FMAs (acc pairs along N, B-cols contiguous).
// grid = (128 M-tiles, 3 weight matrices)
// ---------------------------------------------------------------------------
__global__ void __launch_bounds__(256) qkv_gemm_kernel(
    const float* __restrict__ x, const float* __restrict__ Wq,
    const float* __restrict__ Wk, const float* __restrict__ Wv)
{
    __shared__ float As[8][64];    // A tile transposed: As[k][m]
    __shared__ float Bs[8][128];   // B tile: Bs[k][n]

    const float* W;
    float* out;
    if (blockIdx.y == 0)      { W = Wq; out = g_q; }
    else if (blockIdx.y == 1) { W = Wk; out = g_k; }
    else                      { W = Wv; out = g_v; }

    const int t  = threadIdx.x;
    const int tx = t & 15;          // 16 col groups  -> cols tx*8 .. +7
    const int ty = t >> 4;          // 16 row groups  -> rows ty*4 .. +3
    const int m0 = blockIdx.x * 64;

    // A loader: 64 rows x 8 k = 512 floats, 2 per thread (float2)
    const int arow = t & 63;
    const int acol = (t >> 6) << 1;
    // B loader: 8 rows x 128 cols = 1024 floats, 4 per thread (float4)
    const int brow = t >> 5;
    const int bcol = (t & 31) << 2;

    u64 acc2[4][4];
    #pragma unroll
    for (int i = 0; i < 4; i++)
        #pragma unroll
        for (int j = 0; j < 4; j++) acc2[i][j] = 0ULL;

    for (int k0 = 0; k0 < C_; k0 += 8) {
        float2 a2 = *(const float2*)(x + (size_t)(m0 + arow) * C_ + k0 + acol);
        float4 b4 = *(const float4*)(W + (size_t)(k0 + brow) * H_ + bcol);
        __syncthreads();   // previous tile fully consumed
        As[acol + 0][arow] = a2.x;
        As[acol + 1][arow] = a2.y;
        *(float4*)&Bs[brow][bcol] = b4;
        __syncthreads();
        #pragma unroll
        for (int kk = 0; kk < 8; kk++) {
            float4 af = *(const float4*)&As[kk][ty * 4];
            ulonglong2 b01 = *(const ulonglong2*)&Bs[kk][tx * 8];
            ulonglong2 b23 = *(const ulonglong2*)&Bs[kk][tx * 8 + 4];
            const float a[4] = { af.x, af.y, af.z, af.w };
            #pragma unroll
            for (int i = 0; i < 4; i++) {
                u64 ai = bcast2(a[i]);
                fma2(acc2[i][0], ai, b01.x);
                fma2(acc2[i][1], ai, b01.y);
                fma2(acc2[i][2], ai, b23.x);
                fma2(acc2[i][3], ai, b23.y);
            }
        }
    }

    #pragma unroll
    for (int i = 0; i < 4; i++) {
        float c[8];
        #pragma unroll
        for (int j = 0; j < 4; j++) unpack2(acc2[i][j], c[2*j], c[2*j+1]);
        size_t ro = (size_t)(m0 + ty * 4 + i) * H_ + tx * 8;
        *(float4*)(out + ro)     = make_float4(c[0], c[1], c[2], c[3]);
        *(float4*)(out + ro + 4) = make_float4(c[4], c[5], c[6], c[7]);
    }
}

// ---------------------------------------------------------------------------
// Kernel 2: flash attention, fp32, causal, packed f32x2 math.
// BM = 64 queries / block, BN = 128 keys / tile, 128 threads (16 x 8).
// Thread (tx, ty): S frag 8x8 (rows ty*8+r, cols tx*8+c), O frag 8x8.
// Smem: Q^T[128d][64], K^T[128d][128], V[128][128], P[64][128]  (192 KB).
// Transposed Q/K let the outer-product read a[8]/b[8] as contiguous float4s;
// Q and P reads are warp-broadcast (2 addrs/warp) so LDS stays far under FMA.
// Grid: 32 q-tiles x 4 batches = 128 blocks; block qt does qt/2+1 KV tiles.
// ---------------------------------------------------------------------------
__global__ void __launch_bounds__(128) attn_kernel(float* __restrict__ out)
{
    extern __shared__ float sm[];
    float* QT = sm;                      // [128][64]
    float* KT = QT + 128 * 64;           // [128][128]
    float* Vs = KT + 128 * 128;          // [128][128]
    float* Ps = Vs + 128 * 128;          // [64][128]

    const int b  = blockIdx.y;
    const int qt = blockIdx.x;           // 0..31, tile of 64 query rows
    const int ntiles = (qt >> 1) + 1;    // KV tiles of 128 keys
    const int t  = threadIdx.x;
    const int tx = t & 15;               // cols tx*8 .. +7
    const int ty = t >> 4;               // rows ty*8 .. +7
    const float scale = 0.03125f;        // C^-0.5, C = 1024

    // ---- load Q transposed + pre-scaled: QT[d][row] ----
    {
        const size_t qbase = ((size_t)b * T_ + (size_t)qt * 64) * H_;
        #pragma unroll
        for (int idx = t; idx < 64 * 32; idx += 128) {
            int row = idx & 63, g = idx >> 6;            // g: d-group 0..31
            float4 q = *(const float4*)(g_q + qbase + (size_t)row * H_ + (g << 2));
            QT[(g*4 + 0) * 64 + row] = q.x * scale;
            QT[(g*4 + 1) * 64 + row] = q.y * scale;
            QT[(g*4 + 2) * 64 + row] = q.z * scale;
            QT[(g*4 + 3) * 64 + row] = q.w * scale;
        }
    }

    float m[8], l[8];
    u64 o2[8][4];
    #pragma unroll
    for (int r = 0; r < 8; r++) {
        m[r] = -1e30f; l[r] = 0.f;
        #pragma unroll
        for (int j = 0; j < 4; j++) o2[r][j] = 0ULL;
    }

    for (int j = 0; j < ntiles; j++) {
        __syncthreads();  // prev tile's KT/Vs/Ps reads done (and QT writes on j==0)
        const size_t kb = ((size_t)b * T_ + (size_t)j * 128) * H_;
        // K transposed (lane->row keeps STS conflict-free; gmem hits L2),
        // V row-major (fully coalesced).
        #pragma unroll
        for (int idx = t; idx < 128 * 32; idx += 128) {
            int krow = idx & 127, kg = idx >> 7;
            float4 k4 = *(const float4*)(g_k + kb + (size_t)krow * H_ + (kg << 2));
            KT[(kg*4 + 0) * 128 + krow] = k4.x;
            KT[(kg*4 + 1) * 128 + krow] = k4.y;
            KT[(kg*4 + 2) * 128 + krow] = k4.z;
            KT[(kg*4 + 3) * 128 + krow] = k4.w;
            int vrow = idx >> 5, vg = idx & 31;
            float4 v4 = *(const float4*)(g_v + kb + (size_t)vrow * H_ + (vg << 2));
            *(float4*)&Vs[vrow * 128 + (vg << 2)] = v4;
        }
        __syncthreads();

        // ---- S = Q K^T : outer product over d ----
        u64 s2[8][4];
        #pragma unroll
        for (int r = 0; r < 8; r++)
            #pragma unroll
            for (int c = 0; c < 4; c++) s2[r][c] = 0ULL;

        #pragma unroll 2
        for (int d = 0; d < 128; d++) {
            float4 qa = *(const float4*)&QT[d * 64 + ty * 8];
            float4 qb = *(const float4*)&QT[d * 64 + ty * 8 + 4];
            ulonglong2 k01 = *(const ulonglong2*)&KT[d * 128 + tx * 8];
            ulonglong2 k23 = *(const ulonglong2*)&KT[d * 128 + tx * 8 + 4];
            const float qv[8] = { qa.x, qa.y, qa.z, qa.w, qb.x, qb.y, qb.z, qb.w };
            #pragma unroll
            for (int r = 0; r < 8; r++) {
                u64 qr = bcast2(qv[r]);
                fma2(s2[r][0], qr, k01.x);
                fma2(s2[r][1], qr, k01.y);
                fma2(s2[r][2], qr, k23.x);
                fma2(s2[r][3], qr, k23.y);
            }
        }

        // ---- mask + online softmax (row owned by 16-lane group) ----
        const bool lastt = (j == ntiles - 1);
        const int kc0 = j * 128 + tx * 8;
        #pragma unroll
        for (int r = 0; r < 8; r++) {
            float sv[8];
            #pragma unroll
            for (int c = 0; c < 4; c++) unpack2(s2[r][c], sv[2*c], sv[2*c+1]);
            if (lastt) {
                const int qr = qt * 64 + ty * 8 + r;
                #pragma unroll
                for (int c = 0; c < 8; c++)
                    if (kc0 + c > qr) sv[c] = -1e30f;
            }
            float mx = sv[0];
            #pragma unroll
            for (int c = 1; c < 8; c++) mx = fmaxf(mx, sv[c]);
            #pragma unroll
            for (int off = 1; off < 16; off <<= 1)
                mx = fmaxf(mx, __shfl_xor_sync(0xffffffffu, mx, off));
            float mnew  = fmaxf(m[r], mx);
            float alpha = __expf(m[r] - mnew);
            m[r] = mnew;
            float ls = 0.f;
            #pragma unroll
            for (int c = 0; c < 8; c++) { sv[c] = __expf(sv[c] - mnew); ls += sv[c]; }
            #pragma unroll
            for (int off = 1; off < 16; off <<= 1)
                ls += __shfl_xor_sync(0xffffffffu, ls, off);
            l[r] = l[r] * alpha + ls;
            u64 a2 = bcast2(alpha);
            #pragma unroll
            for (int c = 0; c < 4; c++) mul2(o2[r][c], a2);
            float* prow = &Ps[(ty * 8 + r) * 128 + tx * 8];
            *(float4*)(prow)     = make_float4(sv[0], sv[1], sv[2], sv[3]);
            *(float4*)(prow + 4) = make_float4(sv[4], sv[5], sv[6], sv[7]);
        }
        __syncthreads();

        // ---- O += P @ V : outer product over keys ----
        #pragma unroll 2
        for (int kk = 0; kk < 128; kk++) {
            ulonglong2 v01 = *(const ulonglong2*)&Vs[kk * 128 + tx * 8];
            ulonglong2 v23 = *(const ulonglong2*)&Vs[kk * 128 + tx * 8 + 4];
            #pragma unroll
            for (int r = 0; r < 8; r++) {
                u64 p2 = bcast2(Ps[(ty * 8 + r) * 128 + kk]);   // warp broadcast
                fma2(o2[r][0], p2, v01.x);
                fma2(o2[r][1], p2, v01.y);
                fma2(o2[r][2], p2, v23.x);
                fma2(o2[r][3], p2, v23.y);
            }
        }
    }

    // ---- epilogue: normalize and store ----
    #pragma unroll
    for (int r = 0; r < 8; r++) {
        float inv = 1.0f / l[r];
        float ov[8];
        #pragma unroll
        for (int c = 0; c < 4; c++) unpack2(o2[r][c], ov[2*c], ov[2*c+1]);
        size_t ro = ((size_t)b * T_ + (size_t)qt * 64 + ty * 8 + r) * H_ + tx * 8;
        *(float4*)(out + ro)     = make_float4(ov[0]*inv, ov[1]*inv, ov[2]*inv, ov[3]*inv);
        *(float4*)(out + ro + 4) = make_float4(ov[4]*inv, ov[5]*inv, ov[6]*inv, ov[7]*inv);
    }
}

// ---------------------------------------------------------------------------
// Launch
// ---------------------------------------------------------------------------
extern "C" void kernel_launch(void* const* d_in, const int* in_sizes, int n_in,
                              void* d_out, int out_size)
{
    (void)in_sizes; (void)n_in; (void)out_size;
    const float* x  = (const float*)d_in[0];
    const float* Wq = (const float*)d_in[1];
    const float* Wk = (const float*)d_in[2];
    const float* Wv = (const float*)d_in[3];
    float* out = (float*)d_out;

    // QKV projection: 128 M-tiles x 3 matrices
    qkv_gemm_kernel<<<dim3(128, 3), 256>>>(x, Wq, Wk, Wv);

    // Flash attention: 32 q-tiles (BM=64) x 4 batches
    const int smem_bytes = (128*64 + 128*128 + 128*128 + 64*128) * (int)sizeof(float); // 196608
    cudaFuncSetAttribute(attn_kernel, cudaFuncAttributeMaxDynamicSharedMemorySize, smem_bytes);
    attn_kernel<<<dim3(32, B_), 128, smem_bytes>>>(out);
}

// round 14
// speedup vs baseline: 3.1531x; 3.1531x over previous
#include <cuda_runtime.h>
#include <cuda_bf16.h>
#include <cstdint>

// Problem constants
#define B_   4
#define T_   2048
#define C_   1024
#define H_   128
#define BT_  (B_ * T_)

// ---------------------------------------------------------------------------
// Scratch (__device__ globals per alloc rules)
// ---------------------------------------------------------------------------
__device__ float g_q[BT_ * H_];
__device__ float g_k[BT_ * H_];
__device__ float g_v[BT_ * H_];
// Transposed + hi/lo-split weights: [3 mats][128 n][1024 k] bf16
__device__ __nv_bfloat16 g_wt_hi[3 * H_ * C_];
__device__ __nv_bfloat16 g_wt_lo[3 * H_ * C_];

// ---------------------------------------------------------------------------
// Base-ISA tensor helpers: mma.sync m16n8k16 bf16 (sm_80+, valid on sm_103)
// ---------------------------------------------------------------------------
__device__ __forceinline__ uint32_t smem_u32(const void* p) {
    uint32_t a;
    asm("{ .reg .u64 t; cvta.to.shared.u64 t, %1; cvt.u32.u64 %0, t; }" : "=r"(a) : "l"(p));
    return a;
}
__device__ __forceinline__ void ldm4(uint32_t* r, uint32_t addr) {
    asm volatile("ldmatrix.sync.aligned.m8n8.x4.shared.b16 {%0,%1,%2,%3}, [%4];"
                 : "=r"(r[0]), "=r"(r[1]), "=r"(r[2]), "=r"(r[3]) : "r"(addr));
}
__device__ __forceinline__ void ldm4t(uint32_t* r, uint32_t addr) {
    asm volatile("ldmatrix.sync.aligned.m8n8.x4.trans.shared.b16 {%0,%1,%2,%3}, [%4];"
                 : "=r"(r[0]), "=r"(r[1]), "=r"(r[2]), "=r"(r[3]) : "r"(addr));
}
__device__ __forceinline__ void mma_bf16(float* d, const uint32_t* a, uint32_t b0, uint32_t b1) {
    asm volatile("mma.sync.aligned.m16n8k16.row.col.f32.bf16.bf16.f32 "
                 "{%0,%1,%2,%3}, {%4,%5,%6,%7}, {%8,%9}, {%0,%1,%2,%3};"
                 : "+f"(d[0]), "+f"(d[1]), "+f"(d[2]), "+f"(d[3])
                 : "r"(a[0]), "r"(a[1]), "r"(a[2]), "r"(a[3]), "r"(b0), "r"(b1));
}
// pack two bf16 into b32: first arg -> low 16 bits (memory order / frag low elem)
__device__ __forceinline__ uint32_t pack2(__nv_bfloat16 lo, __nv_bfloat16 hi) {
    return (uint32_t)__bfloat16_as_ushort(lo) | ((uint32_t)__bfloat16_as_ushort(hi) << 16);
}
// split a float4 into bf16-hi (RN) and bf16-lo (residual) packed pairs
__device__ __forceinline__ void split4(float4 v, uint2& hi, uint2& lo) {
    __nv_bfloat16 hx = __float2bfloat16(v.x), hy = __float2bfloat16(v.y);
    __nv_bfloat16 hz = __float2bfloat16(v.z), hw = __float2bfloat16(v.w);
    hi.x = pack2(hx, hy);
    hi.y = pack2(hz, hw);
    lo.x = pack2(__float2bfloat16(v.x - __bfloat162float(hx)),
                 __float2bfloat16(v.y - __bfloat162float(hy)));
    lo.y = pack2(__float2bfloat16(v.z - __bfloat162float(hz)),
                 __float2bfloat16(v.w - __bfloat162float(hw)));
}

// ---------------------------------------------------------------------------
// Kernel 0: transpose + hi/lo split the weights. W[k][n] fp32 -> [n][k] bf16.
// ---------------------------------------------------------------------------
__global__ void __launch_bounds__(256) wt_split_kernel(
    const float* __restrict__ Wq, const float* __restrict__ Wk, const float* __restrict__ Wv)
{
    const int mat = blockIdx.y;
    const float* W = (mat == 0) ? Wq : (mat == 1) ? Wk : Wv;
    const int idx = blockIdx.x * 256 + threadIdx.x;     // 0 .. 131071
    const int n = idx >> 10, k = idx & 1023;
    float w = W[(size_t)k * H_ + n];
    __nv_bfloat16 hi = __float2bfloat16(w);
    float lo = w - __bfloat162float(hi);
    g_wt_hi[(size_t)mat * H_ * C_ + idx] = hi;
    g_wt_lo[(size_t)mat * H_ * C_ + idx] = __float2bfloat16(lo);
}

// ---------------------------------------------------------------------------
// Kernel 1: QKV projection via mma.sync bf16 hi/lo split (fp32 accum regs).
// Block tile 64(M)x128(N), K chunks of 64. 8 warps: wm = w&1 (32 rows),
// wn = w>>1 (32 cols). smem (static 48KB): Ahi/Alo [64][64], Bhi/Blo [128][64],
// 128B rows, XOR-16B swizzle (granule ^= row&7). grid (128 M-tiles, 3 mats).
// ---------------------------------------------------------------------------
__global__ void __launch_bounds__(256) qkv_mma_kernel(const float* __restrict__ x)
{
    __shared__ __align__(128) char sm[49152];   // Ahi@0 Alo@8192 Bhi@16384 Blo@32768
    const uint32_t sb = smem_u32(sm);
    const int t = threadIdx.x, lane = t & 31, w = t >> 5;
    const int wm = w & 1, wn = w >> 1;
    const int m0 = blockIdx.x * 64, mat = blockIdx.y;
    float* out = (mat == 0) ? g_q : (mat == 1) ? g_k : g_v;
    const __nv_bfloat16* wth = g_wt_hi + (size_t)mat * H_ * C_;
    const __nv_bfloat16* wtl = g_wt_lo + (size_t)mat * H_ * C_;

    float acc[2][4][4] = {};

    // loop-invariant ldmatrix lane addressing
    const int a_r  = wm * 32 + (lane & 7) + ((lane & 8) ? 8 : 0);
    const int a_kb = (lane & 16) ? 16 : 0;
    const uint32_t a_sw = ((uint32_t)(a_r & 7)) << 4;
    const int b_n  = wn * 32 + (lane & 7) + ((lane & 16) ? 8 : 0);
    const int b_kb = (lane & 8) ? 16 : 0;
    const uint32_t b_sw = ((uint32_t)(b_n & 7)) << 4;

    for (int c = 0; c < 16; c++) {
        const int k0 = c * 64;
        __syncthreads();
        // A tile: 64x64 fp32 -> split bf16
        #pragma unroll
        for (int i = 0; i < 4; i++) {
            int idx = t + i * 256, r = idx >> 4, k4 = idx & 15;
            float4 a = *(const float4*)(x + (size_t)(m0 + r) * C_ + k0 + k4 * 4);
            uint2 hi, lo; split4(a, hi, lo);
            uint32_t off = (uint32_t)(r * 128) + (((uint32_t)(k4 * 8)) ^ (((uint32_t)r & 7) << 4));
            *(uint2*)(sm + off)        = hi;
            *(uint2*)(sm + 8192 + off) = lo;
        }
        // B tile: 128x64 bf16 (pre-split)
        #pragma unroll
        for (int i = 0; i < 4; i++) {
            int idx = t + i * 256, n = idx >> 3, k8 = idx & 7;
            uint4 hb = *(const uint4*)(wth + (size_t)n * C_ + k0 + k8 * 8);
            uint4 lb = *(const uint4*)(wtl + (size_t)n * C_ + k0 + k8 * 8);
            uint32_t off = (uint32_t)(n * 128) + (((uint32_t)(k8 * 16)) ^ (((uint32_t)n & 7) << 4));
            *(uint4*)(sm + 16384 + off) = hb;
            *(uint4*)(sm + 32768 + off) = lb;
        }
        __syncthreads();
        #pragma unroll
        for (int ks = 0; ks < 4; ks++) {
            uint32_t ah[2][4], al[2][4];
            #pragma unroll
            for (int f = 0; f < 2; f++) {
                uint32_t off = (uint32_t)((a_r + f * 16) * 128) + (((uint32_t)(ks * 32 + a_kb)) ^ a_sw);
                ldm4(ah[f], sb + off);
                ldm4(al[f], sb + 8192 + off);
            }
            #pragma unroll
            for (int half = 0; half < 2; half++) {
                uint32_t off = (uint32_t)((b_n + half * 16) * 128) + (((uint32_t)(ks * 32 + b_kb)) ^ b_sw);
                uint32_t bh[4], bl[4];
                ldm4(bh, sb + 16384 + off);
                ldm4(bl, sb + 32768 + off);
                #pragma unroll
                for (int f = 0; f < 2; f++) {
                    const int j0 = half * 2;
                    mma_bf16(acc[f][j0],     ah[f], bh[0], bh[1]);
                    mma_bf16(acc[f][j0],     ah[f], bl[0], bl[1]);
                    mma_bf16(acc[f][j0],     al[f], bh[0], bh[1]);
                    mma_bf16(acc[f][j0 + 1], ah[f], bh[2], bh[3]);
                    mma_bf16(acc[f][j0 + 1], ah[f], bl[2], bl[3]);
                    mma_bf16(acc[f][j0 + 1], al[f], bh[2], bh[3]);
                }
            }
        }
    }
    const int r = lane >> 2, cc = lane & 3;
    #pragma unroll
    for (int f = 0; f < 2; f++) {
        int row = m0 + wm * 32 + f * 16 + r;
        #pragma unroll
        for (int j = 0; j < 4; j++) {
            int col = wn * 32 + j * 8 + cc * 2;
            *(float2*)(out + (size_t)row * H_ + col)       = make_float2(acc[f][j][0], acc[f][j][1]);
            *(float2*)(out + (size_t)(row + 8) * H_ + col) = make_float2(acc[f][j][2], acc[f][j][3]);
        }
    }
}

// ---------------------------------------------------------------------------
// Kernel 2: flash attention via mma.sync bf16 hi/lo split, fp32 softmax.
// BM=64 queries/block, BN=64 keys/tile, 256 threads = 8 warps:
//   wm = w&3 -> m16 rows wm*16..+15;  wn = w>>2 -> S keys wn*32..+31 / O dims wn*64..+63.
// Cross-warp row max/sum exchanged via tiny smem arrays (two extra syncs/tile).
// P goes through smem as split bf16 and is re-loaded as A-fragments; V is
// consumed with ldmatrix.trans. smem ~113KB (1 CTA/SM; grid 32x4 = 128 blocks).
// R14 fix: P store swizzle now uses the STORE row (row0&7), not the ldmatrix
// address row (lane&7) — that mismatch was R13's rel_err=0.83.
// ---------------------------------------------------------------------------
#define SQ_HI 0
#define SQ_LO 16384
#define SK_HI 32768
#define SK_LO 49152
#define SV_HI 65536
#define SV_LO 81920
#define SP_HI 98304
#define SP_LO 106496
#define SMAXO 114688
#define SSUMO 115200
#define ATT_SMEM 115712

__global__ void __launch_bounds__(256) attn_mma_kernel(float* __restrict__ out)
{
    extern __shared__ __align__(16) char sm[];
    const uint32_t sb = smem_u32(sm);
    const int t = threadIdx.x, lane = t & 31, w = t >> 5;
    const int wm = w & 3, wn = w >> 2;
    const int qt = blockIdx.x, b = blockIdx.y;
    const int r = lane >> 2, cc = lane & 3;
    const float scale = 0.03125f;   // C^-0.5

    // ---- load Q tile (scaled + split), stays resident all tiles ----
    const size_t qb = ((size_t)b * T_ + (size_t)qt * 64) * H_;
    #pragma unroll
    for (int i = 0; i < 8; i++) {
        int idx = t + i * 256, rr = idx >> 5, d4 = idx & 31;
        float4 q = *(const float4*)(g_q + qb + (size_t)rr * H_ + d4 * 4);
        q.x *= scale; q.y *= scale; q.z *= scale; q.w *= scale;
        uint2 hi, lo; split4(q, hi, lo);
        uint32_t off = (uint32_t)(rr * 256) + (((uint32_t)(d4 * 8)) ^ (((uint32_t)rr & 7) << 4));
        *(uint2*)(sm + SQ_HI + off) = hi;
        *(uint2*)(sm + SQ_LO + off) = lo;
    }

    float mrow0 = -1e30f, mrow1 = -1e30f, lrow0 = 0.f, lrow1 = 0.f;
    float o[8][4] = {};

    // loop-invariant ldmatrix lane addressing
    const int qa_r  = wm * 16 + (lane & 7) + ((lane & 8) ? 8 : 0);   // Q / P A-frag rows
    const int qa_kb = (lane & 16) ? 16 : 0;
    const uint32_t qa_sw = ((uint32_t)(qa_r & 7)) << 4;
    const int kb_n  = wn * 32 + (lane & 7) + ((lane & 16) ? 8 : 0);  // K B-frag n
    const int kb_kb = (lane & 8) ? 16 : 0;
    const uint32_t kb_sw = ((uint32_t)(kb_n & 7)) << 4;
    const int vb_k  = (lane & 7) + ((lane & 8) ? 8 : 0);             // V key (trans)
    const int vb_db = (lane & 16) ? 16 : 0;
    const int row0  = wm * 16 + r;
    const uint32_t p_sw = ((uint32_t)(row0 & 7)) << 4;               // store-row swizzle (== (row0+8)&7)
    float* smax = (float*)(sm + SMAXO);
    float* ssum = (float*)(sm + SSUMO);

    const int ntiles = qt + 1;
    for (int j = 0; j < ntiles; j++) {
        __syncthreads();   // prev tile's K/V/P reads done (and Q writes on j==0)
        const size_t kb0 = ((size_t)b * T_ + (size_t)j * 64) * H_;
        #pragma unroll
        for (int i = 0; i < 8; i++) {
            int idx = t + i * 256, rr = idx >> 5, d4 = idx & 31;
            uint32_t off = (uint32_t)(rr * 256) + (((uint32_t)(d4 * 8)) ^ (((uint32_t)rr & 7) << 4));
            float4 k4 = *(const float4*)(g_k + kb0 + (size_t)rr * H_ + d4 * 4);
            uint2 hi, lo; split4(k4, hi, lo);
            *(uint2*)(sm + SK_HI + off) = hi;
            *(uint2*)(sm + SK_LO + off) = lo;
            float4 v4 = *(const float4*)(g_v + kb0 + (size_t)rr * H_ + d4 * 4);
            split4(v4, hi, lo);
            *(uint2*)(sm + SV_HI + off) = hi;
            *(uint2*)(sm + SV_LO + off) = lo;
        }
        __syncthreads();

        // ---- S = Q K^T (4 n8-frags per thread over warp's 32 keys) ----
        float s[4][4] = {};
        #pragma unroll
        for (int ks = 0; ks < 8; ks++) {
            uint32_t qoff = (uint32_t)(qa_r * 256) + (((uint32_t)(ks * 32 + qa_kb)) ^ qa_sw);
            uint32_t qh[4], ql[4];
            ldm4(qh, sb + SQ_HI + qoff);
            ldm4(ql, sb + SQ_LO + qoff);
            #pragma unroll
            for (int half = 0; half < 2; half++) {
                uint32_t koff = (uint32_t)((kb_n + half * 16) * 256) + (((uint32_t)(ks * 32 + kb_kb)) ^ kb_sw);
                uint32_t kh[4], kl[4];
                ldm4(kh, sb + SK_HI + koff);
                ldm4(kl, sb + SK_LO + koff);
                const int j0 = half * 2;
                mma_bf16(s[j0],     qh, kh[0], kh[1]);
                mma_bf16(s[j0],     qh, kl[0], kl[1]);
                mma_bf16(s[j0],     ql, kh[0], kh[1]);
                mma_bf16(s[j0 + 1], qh, kh[2], kh[3]);
                mma_bf16(s[j0 + 1], qh, kl[2], kl[3]);
                mma_bf16(s[j0 + 1], ql, kh[2], kh[3]);
            }
        }

        // ---- causal mask (diagonal tile only: j == qt, same 64-range) ----
        if (j == qt) {
            #pragma unroll
            for (int jf = 0; jf < 4; jf++) {
                int col = wn * 32 + jf * 8 + cc * 2;
                if (col     > row0)     s[jf][0] = -1e30f;
                if (col + 1 > row0)     s[jf][1] = -1e30f;
                if (col     > row0 + 8) s[jf][2] = -1e30f;
                if (col + 1 > row0 + 8) s[jf][3] = -1e30f;
            }
        }

        // ---- local row max -> smem exchange across the 2 key-warps ----
        float mx0 = -1e30f, mx1 = -1e30f;
        #pragma unroll
        for (int jf = 0; jf < 4; jf++) {
            mx0 = fmaxf(mx0, fmaxf(s[jf][0], s[jf][1]));
            mx1 = fmaxf(mx1, fmaxf(s[jf][2], s[jf][3]));
        }
        mx0 = fmaxf(mx0, __shfl_xor_sync(0xffffffffu, mx0, 1));
        mx0 = fmaxf(mx0, __shfl_xor_sync(0xffffffffu, mx0, 2));
        mx1 = fmaxf(mx1, __shfl_xor_sync(0xffffffffu, mx1, 1));
        mx1 = fmaxf(mx1, __shfl_xor_sync(0xffffffffu, mx1, 2));
        if (cc == 0) { smax[row0 * 2 + wn] = mx0; smax[(row0 + 8) * 2 + wn] = mx1; }
        __syncthreads();

        float mn0 = fmaxf(mrow0, fmaxf(smax[row0 * 2],       smax[row0 * 2 + 1]));
        float mn1 = fmaxf(mrow1, fmaxf(smax[(row0 + 8) * 2], smax[(row0 + 8) * 2 + 1]));
        float alpha0 = __expf(mrow0 - mn0), alpha1 = __expf(mrow1 - mn1);
        mrow0 = mn0; mrow1 = mn1;

        float sum0 = 0.f, sum1 = 0.f;
        #pragma unroll
        for (int jf = 0; jf < 4; jf++) {
            float p0 = __expf(s[jf][0] - mn0);
            float p1 = __expf(s[jf][1] - mn0);
            float p2 = __expf(s[jf][2] - mn1);
            float p3 = __expf(s[jf][3] - mn1);
            sum0 += p0 + p1; sum1 += p2 + p3;
            // split + store P to smem (128B rows, XOR swizzle keyed on STORE row)
            int col2 = (wn * 32 + jf * 8 + cc * 2) * 2;   // byte offset of col
            uint32_t off0 = (uint32_t)(row0 * 128)       + (((uint32_t)col2) ^ p_sw);
            uint32_t off1 = (uint32_t)((row0 + 8) * 128) + (((uint32_t)col2) ^ p_sw);
            __nv_bfloat16 h0 = __float2bfloat16(p0), h1 = __float2bfloat16(p1);
            __nv_bfloat16 h2 = __float2bfloat16(p2), h3 = __float2bfloat16(p3);
            *(uint32_t*)(sm + SP_HI + off0) = pack2(h0, h1);
            *(uint32_t*)(sm + SP_HI + off1) = pack2(h2, h3);
            *(uint32_t*)(sm + SP_LO + off0) = pack2(__float2bfloat16(p0 - __bfloat162float(h0)),
                                                    __float2bfloat16(p1 - __bfloat162float(h1)));
            *(uint32_t*)(sm + SP_LO + off1) = pack2(__float2bfloat16(p2 - __bfloat162float(h2)),
                                                    __float2bfloat16(p3 - __bfloat162float(h3)));
        }
        sum0 += __shfl_xor_sync(0xffffffffu, sum0, 1);
        sum0 += __shfl_xor_sync(0xffffffffu, sum0, 2);
        sum1 += __shfl_xor_sync(0xffffffffu, sum1, 1);
        sum1 += __shfl_xor_sync(0xffffffffu, sum1, 2);
        if (cc == 0) { ssum[row0 * 2 + wn] = sum0; ssum[(row0 + 8) * 2 + wn] = sum1; }

        // rescale O while waiting
        #pragma unroll
        for (int jj = 0; jj < 8; jj++) {
            o[jj][0] *= alpha0; o[jj][1] *= alpha0;
            o[jj][2] *= alpha1; o[jj][3] *= alpha1;
        }
        __syncthreads();   // P + sums visible
        lrow0 = lrow0 * alpha0 + ssum[row0 * 2]       + ssum[row0 * 2 + 1];
        lrow1 = lrow1 * alpha1 + ssum[(row0 + 8) * 2] + ssum[(row0 + 8) * 2 + 1];

        // ---- O += P V  (warp covers dims wn*64..+63, full 64 keys) ----
        #pragma unroll
        for (int ks = 0; ks < 4; ks++) {
            uint32_t poff = (uint32_t)(qa_r * 128) + (((uint32_t)(ks * 32 + qa_kb)) ^ qa_sw);
            uint32_t ph[4], pl[4];
            ldm4(ph, sb + SP_HI + poff);
            ldm4(pl, sb + SP_LO + poff);
            const int key = ks * 16 + vb_k;
            const uint32_t v_sw = ((uint32_t)(key & 7)) << 4;
            #pragma unroll
            for (int dd = 0; dd < 4; dd++) {
                uint32_t voff = (uint32_t)(key * 256) +
                                (((uint32_t)((wn * 64 + dd * 16) * 2 + vb_db)) ^ v_sw);
                uint32_t vh[4], vl[4];
                ldm4t(vh, sb + SV_HI + voff);
                ldm4t(vl, sb + SV_LO + voff);
                const int jj = dd * 2;
                mma_bf16(o[jj],     ph, vh[0], vh[1]);
                mma_bf16(o[jj],     ph, vl[0], vl[1]);
                mma_bf16(o[jj],     pl, vh[0], vh[1]);
                mma_bf16(o[jj + 1], ph, vh[2], vh[3]);
                mma_bf16(o[jj + 1], ph, vl[2], vl[3]);
                mma_bf16(o[jj + 1], pl, vh[2], vh[3]);
            }
        }
    }

    // ---- epilogue: normalize and store ----
    const float inv0 = 1.f / lrow0, inv1 = 1.f / lrow1;
    const size_t ob = ((size_t)b * T_ + (size_t)qt * 64) * H_;
    #pragma unroll
    for (int jj = 0; jj < 8; jj++) {
        int col = wn * 64 + jj * 8 + cc * 2;
        *(float2*)(out + ob + (size_t)row0 * H_ + col) =
            make_float2(o[jj][0] * inv0, o[jj][1] * inv0);
        *(float2*)(out + ob + (size_t)(row0 + 8) * H_ + col) =
            make_float2(o[jj][2] * inv1, o[jj][3] * inv1);
    }
}

// ---------------------------------------------------------------------------
// Launch
// ---------------------------------------------------------------------------
extern "C" void kernel_launch(void* const* d_in, const int* in_sizes, int n_in,
                              void* d_out, int out_size)
{
    (void)in_sizes; (void)n_in; (void)out_size;
    const float* x  = (const float*)d_in[0];
    const float* Wq = (const float*)d_in[1];
    const float* Wk = (const float*)d_in[2];
    const float* Wv = (const float*)d_in[3];
    float* out = (float*)d_out;

    // Weight transpose + bf16 hi/lo split
    wt_split_kernel<<<dim3(512, 3), 256>>>(Wq, Wk, Wv);

    // QKV projection on HMMA tensor cores
    qkv_mma_kernel<<<dim3(128, 3), 256>>>(x);

    // Flash attention on HMMA tensor cores
    cudaFuncSetAttribute(attn_mma_kernel, cudaFuncAttributeMaxDynamicSharedMemorySize, ATT_SMEM);
    attn_mma_kernel<<<dim3(32, B_), 256, ATT_SMEM>>>(out);
}

// round 15
// speedup vs baseline: 3.8899x; 1.2337x over previous
#include <cuda_runtime.h>
#include <cuda_bf16.h>
#include <cstdint>

// Problem constants
#define B_   4
#define T_   2048
#define C_   1024
#define H_   128
#define BT_  (B_ * T_)

// ---------------------------------------------------------------------------
// Scratch (__device__ globals per alloc rules)
// ---------------------------------------------------------------------------
// Q/K/V stored pre-split as bf16 hi/lo, row-major [BT][128]
__device__ __nv_bfloat16 g_qhi[BT_ * H_];
__device__ __nv_bfloat16 g_qlo[BT_ * H_];
__device__ __nv_bfloat16 g_khi[BT_ * H_];
__device__ __nv_bfloat16 g_klo[BT_ * H_];
__device__ __nv_bfloat16 g_vhi[BT_ * H_];
__device__ __nv_bfloat16 g_vlo[BT_ * H_];
// Transposed + hi/lo-split weights: [3 mats][128 n][1024 k] bf16 (Wq pre-scaled)
__device__ __nv_bfloat16 g_wt_hi[3 * H_ * C_];
__device__ __nv_bfloat16 g_wt_lo[3 * H_ * C_];
// Split-K partials: unnormalized O per slot + (m, l) per row
__device__ float  g_po[2 * BT_ * H_];
__device__ float2 g_ml[2 * BT_];

// Work-unit table: 48 units per batch, globally sorted by descending tile
// count so wave-1 gets the big ones (wave>=2 block->SM is work-steal).
// entry = qt | (t0 << 8) | (t1 << 16); unit covers KV tiles [t0, t1).
__device__ const uint32_t g_units[48] = {
    31u | (0u<<8) | (16u<<16), 31u | (16u<<8) | (32u<<16), 30u | (15u<<8) | (31u<<16), 15u | (0u<<8) | (16u<<16),
    30u | (0u<<8) | (15u<<16), 29u | (0u<<8) | (15u<<16), 29u | (15u<<8) | (30u<<16), 28u | (14u<<8) | (29u<<16), 14u | (0u<<8) | (15u<<16),
    28u | (0u<<8) | (14u<<16), 27u | (0u<<8) | (14u<<16), 27u | (14u<<8) | (28u<<16), 26u | (13u<<8) | (27u<<16), 13u | (0u<<8) | (14u<<16),
    26u | (0u<<8) | (13u<<16), 25u | (0u<<8) | (13u<<16), 25u | (13u<<8) | (26u<<16), 24u | (12u<<8) | (25u<<16), 12u | (0u<<8) | (13u<<16),
    24u | (0u<<8) | (12u<<16), 23u | (0u<<8) | (12u<<16), 23u | (12u<<8) | (24u<<16), 22u | (11u<<8) | (23u<<16), 11u | (0u<<8) | (12u<<16),
    22u | (0u<<8) | (11u<<16), 21u | (0u<<8) | (11u<<16), 21u | (11u<<8) | (22u<<16), 20u | (10u<<8) | (21u<<16), 10u | (0u<<8) | (11u<<16),
    20u | (0u<<8) | (10u<<16), 19u | (0u<<8) | (10u<<16), 19u | (10u<<8) | (20u<<16), 18u | (9u<<8) | (19u<<16),  9u | (0u<<8) | (10u<<16),
    18u | (0u<<8) | (9u<<16),  17u | (0u<<8) | (9u<<16),  17u | (9u<<8) | (18u<<16),  16u | (8u<<8) | (17u<<16),  8u | (0u<<8) | (9u<<16),
    16u | (0u<<8) | (8u<<16),   7u | (0u<<8) | (8u<<16),
     6u | (0u<<8) | (7u<<16),   5u | (0u<<8) | (6u<<16),   4u | (0u<<8) | (5u<<16),   3u | (0u<<8) | (4u<<16),
     2u | (0u<<8) | (3u<<16),   1u | (0u<<8) | (2u<<16),   0u | (0u<<8) | (1u<<16)
};

// ---------------------------------------------------------------------------
// Base-ISA tensor helpers: mma.sync m16n8k16 bf16 (sm_80+, valid on sm_103)
// ---------------------------------------------------------------------------
__device__ __forceinline__ uint32_t smem_u32(const void* p) {
    uint32_t a;
    asm("{ .reg .u64 t; cvta.to.shared.u64 t, %1; cvt.u32.u64 %0, t; }" : "=r"(a) : "l"(p));
    return a;
}
__device__ __forceinline__ void ldm4(uint32_t* r, uint32_t addr) {
    asm volatile("ldmatrix.sync.aligned.m8n8.x4.shared.b16 {%0,%1,%2,%3}, [%4];"
                 : "=r"(r[0]), "=r"(r[1]), "=r"(r[2]), "=r"(r[3]) : "r"(addr));
}
__device__ __forceinline__ void ldm4t(uint32_t* r, uint32_t addr) {
    asm volatile("ldmatrix.sync.aligned.m8n8.x4.trans.shared.b16 {%0,%1,%2,%3}, [%4];"
                 : "=r"(r[0]), "=r"(r[1]), "=r"(r[2]), "=r"(r[3]) : "r"(addr));
}
__device__ __forceinline__ void mma_bf16(float* d, const uint32_t* a, uint32_t b0, uint32_t b1) {
    asm volatile("mma.sync.aligned.m16n8k16.row.col.f32.bf16.bf16.f32 "
                 "{%0,%1,%2,%3}, {%4,%5,%6,%7}, {%8,%9}, {%0,%1,%2,%3};"
                 : "+f"(d[0]), "+f"(d[1]), "+f"(d[2]), "+f"(d[3])
                 : "r"(a[0]), "r"(a[1]), "r"(a[2]), "r"(a[3]), "r"(b0), "r"(b1));
}
__device__ __forceinline__ uint32_t pack2(__nv_bfloat16 lo, __nv_bfloat16 hi) {
    return (uint32_t)__bfloat16_as_ushort(lo) | ((uint32_t)__bfloat16_as_ushort(hi) << 16);
}
__device__ __forceinline__ void split4(float4 v, uint2& hi, uint2& lo) {
    __nv_bfloat16 hx = __float2bfloat16(v.x), hy = __float2bfloat16(v.y);
    __nv_bfloat16 hz = __float2bfloat16(v.z), hw = __float2bfloat16(v.w);
    hi.x = pack2(hx, hy);
    hi.y = pack2(hz, hw);
    lo.x = pack2(__float2bfloat16(v.x - __bfloat162float(hx)),
                 __float2bfloat16(v.y - __bfloat162float(hy)));
    lo.y = pack2(__float2bfloat16(v.z - __bfloat162float(hz)),
                 __float2bfloat16(v.w - __bfloat162float(hw)));
}
// split a scalar pair into packed hi / lo words
__device__ __forceinline__ void split2(float a, float b, uint32_t& hi, uint32_t& lo) {
    __nv_bfloat16 ha = __float2bfloat16(a), hb = __float2bfloat16(b);
    hi = pack2(ha, hb);
    lo = pack2(__float2bfloat16(a - __bfloat162float(ha)),
               __float2bfloat16(b - __bfloat162float(hb)));
}

// ---------------------------------------------------------------------------
// Kernel 0: transpose + hi/lo split the weights (Wq pre-scaled by C^-0.5).
// ---------------------------------------------------------------------------
__global__ void __launch_bounds__(256) wt_split_kernel(
    const float* __restrict__ Wq, const float* __restrict__ Wk, const float* __restrict__ Wv)
{
    const int mat = blockIdx.y;
    const float* W = (mat == 0) ? Wq : (mat == 1) ? Wk : Wv;
    const int idx = blockIdx.x * 256 + threadIdx.x;     // 0 .. 131071
    const int n = idx >> 10, k = idx & 1023;
    float w = W[(size_t)k * H_ + n];
    if (mat == 0) w *= 0.03125f;                        // fold softmax scale into Wq
    __nv_bfloat16 hi = __float2bfloat16(w);
    float lo = w - __bfloat162float(hi);
    g_wt_hi[(size_t)mat * H_ * C_ + idx] = hi;
    g_wt_lo[(size_t)mat * H_ * C_ + idx] = __float2bfloat16(lo);
}

// ---------------------------------------------------------------------------
// Kernel 1: QKV projection via mma.sync bf16 hi/lo split (fp32 accum regs).
// Block tile 64(M)x128(N), K chunks of 64, register-prefetch of chunk c+1
// across the compute of chunk c. Epilogue stores split bf16 hi/lo directly.
// grid (128 M-tiles, 3 mats), 256 threads.
// ---------------------------------------------------------------------------
__global__ void __launch_bounds__(256) qkv_mma_kernel(const float* __restrict__ x)
{
    __shared__ __align__(128) char sm[49152];   // Ahi@0 Alo@8192 Bhi@16384 Blo@32768
    const uint32_t sb = smem_u32(sm);
    const int t = threadIdx.x, lane = t & 31, w = t >> 5;
    const int wm = w & 1, wn = w >> 1;
    const int m0 = blockIdx.x * 64, mat = blockIdx.y;
    __nv_bfloat16* ohi = (mat == 0) ? g_qhi : (mat == 1) ? g_khi : g_vhi;
    __nv_bfloat16* olo = (mat == 0) ? g_qlo : (mat == 1) ? g_klo : g_vlo;
    const __nv_bfloat16* wth = g_wt_hi + (size_t)mat * H_ * C_;
    const __nv_bfloat16* wtl = g_wt_lo + (size_t)mat * H_ * C_;

    float acc[2][4][4] = {};

    // loop-invariant ldmatrix lane addressing
    const int a_r  = wm * 32 + (lane & 7) + ((lane & 8) ? 8 : 0);
    const int a_kb = (lane & 16) ? 16 : 0;
    const uint32_t a_sw = ((uint32_t)(a_r & 7)) << 4;
    const int b_n  = wn * 32 + (lane & 7) + ((lane & 16) ? 8 : 0);
    const int b_kb = (lane & 8) ? 16 : 0;
    const uint32_t b_sw = ((uint32_t)(b_n & 7)) << 4;

    // loader index mapping (fixed per thread)
    const int la_r = t >> 2,      la_k4 = t & 3;    // A: idx = t + i*256 -> r=idx>>4 … recompute inline
    (void)la_r; (void)la_k4;

    // ---- prefetch chunk 0 ----
    float4 pa[4];
    uint4  phb[4], plb[4];
    #pragma unroll
    for (int i = 0; i < 4; i++) {
        int idx = t + i * 256, r = idx >> 4, k4 = idx & 15;
        pa[i] = *(const float4*)(x + (size_t)(m0 + r) * C_ + k4 * 4);
    }
    #pragma unroll
    for (int i = 0; i < 4; i++) {
        int idx = t + i * 256, n = idx >> 3, k8 = idx & 7;
        phb[i] = *(const uint4*)(wth + (size_t)n * C_ + k8 * 8);
        plb[i] = *(const uint4*)(wtl + (size_t)n * C_ + k8 * 8);
    }

    for (int c = 0; c < 16; c++) {
        __syncthreads();
        // store prefetched chunk c to smem
        #pragma unroll
        for (int i = 0; i < 4; i++) {
            int idx = t + i * 256, r = idx >> 4, k4 = idx & 15;
            uint2 hi, lo; split4(pa[i], hi, lo);
            uint32_t off = (uint32_t)(r * 128) + (((uint32_t)(k4 * 8)) ^ (((uint32_t)r & 7) << 4));
            *(uint2*)(sm + off)        = hi;
            *(uint2*)(sm + 8192 + off) = lo;
        }
        #pragma unroll
        for (int i = 0; i < 4; i++) {
            int idx = t + i * 256, n = idx >> 3, k8 = idx & 7;
            uint32_t off = (uint32_t)(n * 128) + (((uint32_t)(k8 * 16)) ^ (((uint32_t)n & 7) << 4));
            *(uint4*)(sm + 16384 + off) = phb[i];
            *(uint4*)(sm + 32768 + off) = plb[i];
        }
        __syncthreads();

        // issue prefetch for chunk c+1 (overlaps the MMA work below)
        if (c < 15) {
            const int k0 = (c + 1) * 64;
            #pragma unroll
            for (int i = 0; i < 4; i++) {
                int idx = t + i * 256, r = idx >> 4, k4 = idx & 15;
                pa[i] = *(const float4*)(x + (size_t)(m0 + r) * C_ + k0 + k4 * 4);
            }
            #pragma unroll
            for (int i = 0; i < 4; i++) {
                int idx = t + i * 256, n = idx >> 3, k8 = idx & 7;
                phb[i] = *(const uint4*)(wth + (size_t)n * C_ + k0 + k8 * 8);
                plb[i] = *(const uint4*)(wtl + (size_t)n * C_ + k0 + k8 * 8);
            }
        }

        #pragma unroll
        for (int ks = 0; ks < 4; ks++) {
            uint32_t ah[2][4], al[2][4];
            #pragma unroll
            for (int f = 0; f < 2; f++) {
                uint32_t off = (uint32_t)((a_r + f * 16) * 128) + (((uint32_t)(ks * 32 + a_kb)) ^ a_sw);
                ldm4(ah[f], sb + off);
                ldm4(al[f], sb + 8192 + off);
            }
            #pragma unroll
            for (int half = 0; half < 2; half++) {
                uint32_t off = (uint32_t)((b_n + half * 16) * 128) + (((uint32_t)(ks * 32 + b_kb)) ^ b_sw);
                uint32_t bh[4], bl[4];
                ldm4(bh, sb + 16384 + off);
                ldm4(bl, sb + 32768 + off);
                #pragma unroll
                for (int f = 0; f < 2; f++) {
                    const int j0 = half * 2;
                    mma_bf16(acc[f][j0],     ah[f], bh[0], bh[1]);
                    mma_bf16(acc[f][j0],     ah[f], bl[0], bl[1]);
                    mma_bf16(acc[f][j0],     al[f], bh[0], bh[1]);
                    mma_bf16(acc[f][j0 + 1], ah[f], bh[2], bh[3]);
                    mma_bf16(acc[f][j0 + 1], ah[f], bl[2], bl[3]);
                    mma_bf16(acc[f][j0 + 1], al[f], bh[2], bh[3]);
                }
            }
        }
    }

    // epilogue: split fp32 result into bf16 hi/lo and store packed
    const int r = lane >> 2, cc = lane & 3;
    uint32_t* ohi32 = (uint32_t*)ohi;
    uint32_t* olo32 = (uint32_t*)olo;
    #pragma unroll
    for (int f = 0; f < 2; f++) {
        int row = m0 + wm * 32 + f * 16 + r;
        #pragma unroll
        for (int j = 0; j < 4; j++) {
            int col = wn * 32 + j * 8 + cc * 2;
            uint32_t h0, l0, h1, l1;
            split2(acc[f][j][0], acc[f][j][1], h0, l0);
            split2(acc[f][j][2], acc[f][j][3], h1, l1);
            ohi32[(size_t)row * 64 + (col >> 1)]       = h0;
            olo32[(size_t)row * 64 + (col >> 1)]       = l0;
            ohi32[(size_t)(row + 8) * 64 + (col >> 1)] = h1;
            olo32[(size_t)(row + 8) * 64 + (col >> 1)] = l1;
        }
    }
}

// ---------------------------------------------------------------------------
// Kernel 2: flash attention via mma.sync bf16 hi/lo split, fp32 softmax.
// Split-K work units (<=16 KV tiles each) from g_units, 1-D grid of 192:
// unit g -> batch = g & 3, entry = g_units[g >> 2]. Full-range units write
// normalized output directly; heavy halves write unnormalized O + (m,l) to
// slot 0/1, merged by attn_combine_kernel.
// ---------------------------------------------------------------------------
#define SQ_HI 0
#define SQ_LO 16384
#define SK_HI 32768
#define SK_LO 49152
#define SV_HI 65536
#define SV_LO 81920
#define SP_HI 98304
#define SP_LO 106496
#define SMAXO 114688
#define SSUMO 115200
#define ATT_SMEM 115712

__global__ void __launch_bounds__(256) attn_mma_kernel(float* __restrict__ out)
{
    extern __shared__ __align__(16) char sm[];
    const uint32_t sb = smem_u32(sm);
    const int t = threadIdx.x, lane = t & 31, w = t >> 5;
    const int wm = w & 3, wn = w >> 2;
    const int g = blockIdx.x;
    const int b = g & 3;
    const uint32_t ent = g_units[g >> 2];
    const int qt = (int)(ent & 255u);
    const int t0 = (int)((ent >> 8) & 255u);
    const int t1 = (int)((ent >> 16) & 255u);
    const bool full = (t0 == 0) && (t1 == qt + 1);
    const int slot = (t0 == 0) ? 0 : 1;
    const int r = lane >> 2, cc = lane & 3;

    // ---- load Q tile (pre-split bf16, scale folded into Wq) ----
    const size_t qrow0 = (size_t)b * T_ + (size_t)qt * 64;
    #pragma unroll
    for (int i = 0; i < 8; i++) {
        int idx = t + i * 256;
        int a = idx >> 10, rem = idx & 1023, rr = rem >> 4, g16 = rem & 15;
        const __nv_bfloat16* src = (a == 0) ? g_qhi : g_qlo;
        uint4 v = *(const uint4*)(src + (qrow0 + rr) * H_ + g16 * 8);
        uint32_t off = (uint32_t)(a * 16384) + (uint32_t)(rr * 256) +
                       (((uint32_t)(g16 * 16)) ^ (((uint32_t)rr & 7) << 4));
        *(uint4*)(sm + off) = v;
    }

    float mrow0 = -1e30f, mrow1 = -1e30f, lrow0 = 0.f, lrow1 = 0.f;
    float o[8][4] = {};

    // loop-invariant ldmatrix lane addressing
    const int qa_r  = wm * 16 + (lane & 7) + ((lane & 8) ? 8 : 0);
    const int qa_kb = (lane & 16) ? 16 : 0;
    const uint32_t qa_sw = ((uint32_t)(qa_r & 7)) << 4;
    const int kb_n  = wn * 32 + (lane & 7) + ((lane & 16) ? 8 : 0);
    const int kb_kb = (lane & 8) ? 16 : 0;
    const uint32_t kb_sw = ((uint32_t)(kb_n & 7)) << 4;
    const int vb_k  = (lane & 7) + ((lane & 8) ? 8 : 0);
    const int vb_db = (lane & 16) ? 16 : 0;
    const int row0  = wm * 16 + r;
    const uint32_t p_sw = ((uint32_t)(row0 & 7)) << 4;
    float* smax = (float*)(sm + SMAXO);
    float* ssum = (float*)(sm + SSUMO);

    for (int j = t0; j < t1; j++) {
        __syncthreads();
        const size_t krow0 = (size_t)b * T_ + (size_t)j * 64;
        #pragma unroll
        for (int i = 0; i < 16; i++) {
            int idx = t + i * 256;
            int a = idx >> 10, rem = idx & 1023, rr = rem >> 4, g16 = rem & 15;
            const __nv_bfloat16* src = (a == 0) ? g_khi : (a == 1) ? g_klo : (a == 2) ? g_vhi : g_vlo;
            uint4 v = *(const uint4*)(src + (krow0 + rr) * H_ + g16 * 8);
            uint32_t off = (uint32_t)(SK_HI + a * 16384) + (uint32_t)(rr * 256) +
                           (((uint32_t)(g16 * 16)) ^ (((uint32_t)rr & 7) << 4));
            *(uint4*)(sm + off) = v;
        }
        __syncthreads();

        // ---- S = Q K^T ----
        float s[4][4] = {};
        #pragma unroll
        for (int ks = 0; ks < 8; ks++) {
            uint32_t qoff = (uint32_t)(qa_r * 256) + (((uint32_t)(ks * 32 + qa_kb)) ^ qa_sw);
            uint32_t qh[4], ql[4];
            ldm4(qh, sb + SQ_HI + qoff);
            ldm4(ql, sb + SQ_LO + qoff);
            #pragma unroll
            for (int half = 0; half < 2; half++) {
                uint32_t koff = (uint32_t)((kb_n + half * 16) * 256) + (((uint32_t)(ks * 32 + kb_kb)) ^ kb_sw);
                uint32_t kh[4], kl[4];
                ldm4(kh, sb + SK_HI + koff);
                ldm4(kl, sb + SK_LO + koff);
                const int j0 = half * 2;
                mma_bf16(s[j0],     qh, kh[0], kh[1]);
                mma_bf16(s[j0],     qh, kl[0], kl[1]);
                mma_bf16(s[j0],     ql, kh[0], kh[1]);
                mma_bf16(s[j0 + 1], qh, kh[2], kh[3]);
                mma_bf16(s[j0 + 1], qh, kl[2], kl[3]);
                mma_bf16(s[j0 + 1], ql, kh[2], kh[3]);
            }
        }

        // ---- causal mask (diagonal tile only; only last unit reaches it) ----
        if (j == qt) {
            #pragma unroll
            for (int jf = 0; jf < 4; jf++) {
                int col = wn * 32 + jf * 8 + cc * 2;
                if (col     > row0)     s[jf][0] = -1e30f;
                if (col + 1 > row0)     s[jf][1] = -1e30f;
                if (col     > row0 + 8) s[jf][2] = -1e30f;
                if (col + 1 > row0 + 8) s[jf][3] = -1e30f;
            }
        }

        // ---- online softmax (cross-warp max/sum via smem) ----
        float mx0 = -1e30f, mx1 = -1e30f;
        #pragma unroll
        for (int jf = 0; jf < 4; jf++) {
            mx0 = fmaxf(mx0, fmaxf(s[jf][0], s[jf][1]));
            mx1 = fmaxf(mx1, fmaxf(s[jf][2], s[jf][3]));
        }
        mx0 = fmaxf(mx0, __shfl_xor_sync(0xffffffffu, mx0, 1));
        mx0 = fmaxf(mx0, __shfl_xor_sync(0xffffffffu, mx0, 2));
        mx1 = fmaxf(mx1, __shfl_xor_sync(0xffffffffu, mx1, 1));
        mx1 = fmaxf(mx1, __shfl_xor_sync(0xffffffffu, mx1, 2));
        if (cc == 0) { smax[row0 * 2 + wn] = mx0; smax[(row0 + 8) * 2 + wn] = mx1; }
        __syncthreads();

        float mn0 = fmaxf(mrow0, fmaxf(smax[row0 * 2],       smax[row0 * 2 + 1]));
        float mn1 = fmaxf(mrow1, fmaxf(smax[(row0 + 8) * 2], smax[(row0 + 8) * 2 + 1]));
        float alpha0 = __expf(mrow0 - mn0), alpha1 = __expf(mrow1 - mn1);
        mrow0 = mn0; mrow1 = mn1;

        float sum0 = 0.f, sum1 = 0.f;
        #pragma unroll
        for (int jf = 0; jf < 4; jf++) {
            float p0 = __expf(s[jf][0] - mn0);
            float p1 = __expf(s[jf][1] - mn0);
            float p2 = __expf(s[jf][2] - mn1);
            float p3 = __expf(s[jf][3] - mn1);
            sum0 += p0 + p1; sum1 += p2 + p3;
            int col2 = (wn * 32 + jf * 8 + cc * 2) * 2;
            uint32_t off0 = (uint32_t)(row0 * 128)       + (((uint32_t)col2) ^ p_sw);
            uint32_t off1 = (uint32_t)((row0 + 8) * 128) + (((uint32_t)col2) ^ p_sw);
            uint32_t ph0, pl0, ph1, pl1;
            split2(p0, p1, ph0, pl0);
            split2(p2, p3, ph1, pl1);
            *(uint32_t*)(sm + SP_HI + off0) = ph0;
            *(uint32_t*)(sm + SP_HI + off1) = ph1;
            *(uint32_t*)(sm + SP_LO + off0) = pl0;
            *(uint32_t*)(sm + SP_LO + off1) = pl1;
        }
        sum0 += __shfl_xor_sync(0xffffffffu, sum0, 1);
        sum0 += __shfl_xor_sync(0xffffffffu, sum0, 2);
        sum1 += __shfl_xor_sync(0xffffffffu, sum1, 1);
        sum1 += __shfl_xor_sync(0xffffffffu, sum1, 2);
        if (cc == 0) { ssum[row0 * 2 + wn] = sum0; ssum[(row0 + 8) * 2 + wn] = sum1; }

        #pragma unroll
        for (int jj = 0; jj < 8; jj++) {
            o[jj][0] *= alpha0; o[jj][1] *= alpha0;
            o[jj][2] *= alpha1; o[jj][3] *= alpha1;
        }
        __syncthreads();
        lrow0 = lrow0 * alpha0 + ssum[row0 * 2]       + ssum[row0 * 2 + 1];
        lrow1 = lrow1 * alpha1 + ssum[(row0 + 8) * 2] + ssum[(row0 + 8) * 2 + 1];

        // ---- O += P V ----
        #pragma unroll
        for (int ks = 0; ks < 4; ks++) {
            uint32_t poff = (uint32_t)(qa_r * 128) + (((uint32_t)(ks * 32 + qa_kb)) ^ qa_sw);
            uint32_t ph[4], pl[4];
            ldm4(ph, sb + SP_HI + poff);
            ldm4(pl, sb + SP_LO + poff);
            const int key = ks * 16 + vb_k;
            const uint32_t v_sw = ((uint32_t)(key & 7)) << 4;
            #pragma unroll
            for (int dd = 0; dd < 4; dd++) {
                uint32_t voff = (uint32_t)(SV_HI - SV_HI) + (uint32_t)(key * 256) +
                                (((uint32_t)((wn * 64 + dd * 16) * 2 + vb_db)) ^ v_sw);
                uint32_t vh[4], vl[4];
                ldm4t(vh, sb + SV_HI + voff);
                ldm4t(vl, sb + SV_LO + voff);
                const int jj = dd * 2;
                mma_bf16(o[jj],     ph, vh[0], vh[1]);
                mma_bf16(o[jj],     ph, vl[0], vl[1]);
                mma_bf16(o[jj],     pl, vh[0], vh[1]);
                mma_bf16(o[jj + 1], ph, vh[2], vh[3]);
                mma_bf16(o[jj + 1], ph, vl[2], vl[3]);
                mma_bf16(o[jj + 1], pl, vh[2], vh[3]);
            }
        }
    }

    // ---- epilogue ----
    const size_t grow0 = qrow0 + row0;
    if (full) {
        const float inv0 = 1.f / lrow0, inv1 = 1.f / lrow1;
        #pragma unroll
        for (int jj = 0; jj < 8; jj++) {
            int col = wn * 64 + jj * 8 + cc * 2;
            *(float2*)(out + grow0 * H_ + col) =
                make_float2(o[jj][0] * inv0, o[jj][1] * inv0);
            *(float2*)(out + (grow0 + 8) * H_ + col) =
                make_float2(o[jj][2] * inv1, o[jj][3] * inv1);
        }
    } else {
        float* po = g_po + (size_t)slot * BT_ * H_;
        #pragma unroll
        for (int jj = 0; jj < 8; jj++) {
            int col = wn * 64 + jj * 8 + cc * 2;
            *(float2*)(po + grow0 * H_ + col)       = make_float2(o[jj][0], o[jj][1]);
            *(float2*)(po + (grow0 + 8) * H_ + col) = make_float2(o[jj][2], o[jj][3]);
        }
        if (wn == 0 && cc == 0) {
            g_ml[(size_t)slot * BT_ + grow0]     = make_float2(mrow0, lrow0);
            g_ml[(size_t)slot * BT_ + grow0 + 8] = make_float2(mrow1, lrow1);
        }
    }
}

// ---------------------------------------------------------------------------
// Kernel 3: merge the two split-K partials for heavy rows (qt >= 16, i.e.
// local rows 1024..2047 of each batch). 512 blocks x 256 threads, float4 each.
// ---------------------------------------------------------------------------
__global__ void __launch_bounds__(256) attn_combine_kernel(float* __restrict__ out)
{
    int idx = blockIdx.x * 256 + threadIdx.x;            // 0 .. 131071
    int b = idx >> 15;                                   // 1024 rows * 32 f4-cols
    int rem = idx & 32767;
    int rl = rem >> 5, c4 = rem & 31;
    size_t row = (size_t)b * T_ + 1024 + rl;
    float2 ml0 = g_ml[row];
    float2 ml1 = g_ml[BT_ + row];
    float M = fmaxf(ml0.x, ml1.x);
    float a0 = __expf(ml0.x - M), a1 = __expf(ml1.x - M);
    float inv = 1.f / (ml0.y * a0 + ml1.y * a1);
    float4 p0 = *(const float4*)(g_po + row * H_ + c4 * 4);
    float4 p1 = *(const float4*)(g_po + (size_t)BT_ * H_ + row * H_ + c4 * 4);
    *(float4*)(out + row * H_ + c4 * 4) = make_float4(
        (p0.x * a0 + p1.x * a1) * inv,
        (p0.y * a0 + p1.y * a1) * inv,
        (p0.z * a0 + p1.z * a1) * inv,
        (p0.w * a0 + p1.w * a1) * inv);
}

// ---------------------------------------------------------------------------
// Launch
// ---------------------------------------------------------------------------
extern "C" void kernel_launch(void* const* d_in, const int* in_sizes, int n_in,
                              void* d_out, int out_size)
{
    (void)in_sizes; (void)n_in; (void)out_size;
    const float* x  = (const float*)d_in[0];
    const float* Wq = (const float*)d_in[1];
    const float* Wk = (const float*)d_in[2];
    const float* Wv = (const float*)d_in[3];
    float* out = (float*)d_out;

    // Weight transpose + bf16 hi/lo split (Wq pre-scaled)
    wt_split_kernel<<<dim3(512, 3), 256>>>(Wq, Wk, Wv);

    // QKV projection on HMMA tensor cores -> pre-split bf16 Q/K/V
    qkv_mma_kernel<<<dim3(128, 3), 256>>>(x);

    // Flash attention, split-K balanced units
    cudaFuncSetAttribute(attn_mma_kernel, cudaFuncAttributeMaxDynamicSharedMemorySize, ATT_SMEM);
    attn_mma_kernel<<<192, 256, ATT_SMEM>>>(out);

    // Merge heavy-row partials
    attn_combine_kernel<<<512, 256>>>(out);
}